// round 8
// baseline (speedup 1.0000x reference)
#include <cuda_runtime.h>
#include <cstdint>
#include <math.h>

// Problem constants (fixed by the reference): N=8192 nodes, F=512 features, H=2.
#define NNODE 8192
#define FDIM  512
#define C2    1024

// ---------------- scratch (static __device__ — no allocations) ----------------
__device__ float g_C [(size_t)NNODE * C2];     // X @ W            [8192,1024]  33.5 MB
__device__ float g_Wh[(size_t)NNODE * FDIM];   // Wh               [8192,512]   16 MB
__device__ float g_T [(size_t)NNODE * FDIM];   // tanh(Wh+Ws+b)    [8192,512]   16 MB
__device__ float g_S [(size_t)NNODE * NNODE];  // scores/attn      [8192,8192]  268 MB
__device__ float g_O [(size_t)NNODE * FDIM];   // attn@Wh + X      [8192,512]   16 MB
__device__ float g_psum[32 * FDIM];
__device__ float g_psq [32 * FDIM];
__device__ float g_mean[FDIM];
__device__ float g_rstd[FDIM];

// ---------------- 128x128x8 fp32 GEMM, 256 threads, 8x8 microtiles ----------------
// TRANSB=false: C[M,N] = A[M,K] @ B[K,N]   (+ optional residual)
// TRANSB=true : C[M,N] = A[M,K] @ B[N,K]^T
// All of M,N multiples of 128; K multiple of 8 (holds for every call here).
template<bool TRANSB>
__global__ __launch_bounds__(256, 2)
void sgemm128(const float* __restrict__ A, const float* __restrict__ B,
              float* __restrict__ C, const float* __restrict__ resid,
              int M, int N, int K)
{
    __shared__ float As[8][132];   // pad 132: conflict-free transposed stores
    __shared__ float Bs[8][132];

    const int tid = threadIdx.x;
    const int bx = blockIdx.x, by = blockIdx.y;
    const int tx = tid & 15, ty = tid >> 4;

    float acc[8][8];
#pragma unroll
    for (int i = 0; i < 8; i++)
#pragma unroll
        for (int j = 0; j < 8; j++) acc[i][j] = 0.f;

    // A tile loader: 128 rows x 8 K-cols, one float4 per thread, stored transposed.
    const int aRow = tid >> 1;
    const int aCol = (tid & 1) * 4;
    const float* Ap = A + (size_t)(by * 128 + aRow) * K + aCol;

    const float* Bp;
    int bRow, bCol;
    if (TRANSB) {
        bRow = tid >> 1; bCol = (tid & 1) * 4;          // B[N,K]: like A
        Bp = B + (size_t)(bx * 128 + bRow) * K + bCol;
    } else {
        bRow = tid >> 5; bCol = (tid & 31) * 4;         // B[K,N]: 8 rows x 128 cols
        Bp = B + (size_t)bRow * N + (size_t)bx * 128 + bCol;
    }

    // prefetch first slab
    float4 av = *(const float4*)Ap;
    float4 bv = *(const float4*)Bp;
    Ap += 8;
    Bp += TRANSB ? 8 : (size_t)8 * N;

    for (int k0 = 0; k0 < K; k0 += 8) {
        __syncthreads();
        As[aCol + 0][aRow] = av.x;
        As[aCol + 1][aRow] = av.y;
        As[aCol + 2][aRow] = av.z;
        As[aCol + 3][aRow] = av.w;
        if (TRANSB) {
            Bs[bCol + 0][bRow] = bv.x;
            Bs[bCol + 1][bRow] = bv.y;
            Bs[bCol + 2][bRow] = bv.z;
            Bs[bCol + 3][bRow] = bv.w;
        } else {
            *(float4*)&Bs[bRow][bCol] = bv;
        }
        __syncthreads();

        if (k0 + 8 < K) {   // prefetch next slab: LDG latency overlaps compute
            av = *(const float4*)Ap;
            bv = *(const float4*)Bp;
            Ap += 8;
            Bp += TRANSB ? 8 : (size_t)8 * N;
        }

#pragma unroll
        for (int kk = 0; kk < 8; kk++) {
            float4 a0 = *(const float4*)&As[kk][ty * 4];
            float4 a1 = *(const float4*)&As[kk][ty * 4 + 64];
            float4 b0 = *(const float4*)&Bs[kk][tx * 4];
            float4 b1 = *(const float4*)&Bs[kk][tx * 4 + 64];
            float am[8] = {a0.x, a0.y, a0.z, a0.w, a1.x, a1.y, a1.z, a1.w};
            float bn[8] = {b0.x, b0.y, b0.z, b0.w, b1.x, b1.y, b1.z, b1.w};
#pragma unroll
            for (int i = 0; i < 8; i++)
#pragma unroll
                for (int j = 0; j < 8; j++)
                    acc[i][j] += am[i] * bn[j];
        }
    }

    const int row0 = by * 128, col0 = bx * 128;
    const int c0 = tx * 4, c1 = tx * 4 + 64;
#pragma unroll
    for (int i = 0; i < 8; i++) {
        int r = row0 + ty * 4 + (i < 4 ? i : i + 60);   // rows {t4..t4+3, t4+64..+67}
        size_t base = (size_t)r * N + col0;
        float4 v0 = make_float4(acc[i][0], acc[i][1], acc[i][2], acc[i][3]);
        float4 v1 = make_float4(acc[i][4], acc[i][5], acc[i][6], acc[i][7]);
        if (resid) {
            float4 r0 = *(const float4*)&resid[base + c0];
            float4 r1 = *(const float4*)&resid[base + c1];
            v0.x += r0.x; v0.y += r0.y; v0.z += r0.z; v0.w += r0.w;
            v1.x += r1.x; v1.y += r1.y; v1.z += r1.z; v1.w += r1.w;
        }
        *(float4*)&C[base + c0] = v0;
        *(float4*)&C[base + c1] = v1;
    }
}

// ---------------- split C -> Wh and T = tanh(Wh + Ws + bias) ----------------
__global__ void prep_kernel(const float* __restrict__ aw, const float* __restrict__ ab)
{
    const float bias = aw[0] + ab[0];
    int idx = blockIdx.x * blockDim.x + threadIdx.x;
    int row = idx >> 9, col = idx & 511;
    float wh = g_C[(size_t)row * C2 + col];
    float ws = g_C[(size_t)row * C2 + col + FDIM];
    g_Wh[idx] = wh;
    g_T[idx]  = tanhf(wh + ws + bias);
}

// ---------------- in-place row softmax (online max/sum, 1 block per row) ------
__global__ void softmax_row(float* __restrict__ S, int N)
{
    const int row = blockIdx.x;
    float* p = S + (size_t)row * N;
    const int tid = threadIdx.x;

    float m = -1e30f, s = 0.f;
    for (int i = tid; i < N; i += 256) {
        float x = p[i];
        float mn = fmaxf(m, x);
        s = s * __expf(m - mn) + __expf(x - mn);
        m = mn;
    }
    __shared__ float sm[256], ss[256];
    sm[tid] = m; ss[tid] = s;
    __syncthreads();
    for (int off = 128; off > 0; off >>= 1) {
        if (tid < off) {
            float m2 = sm[tid + off], s2 = ss[tid + off];
            float mn = fmaxf(sm[tid], m2);
            ss[tid] = ss[tid] * __expf(sm[tid] - mn) + s2 * __expf(m2 - mn);
            sm[tid] = mn;
        }
        __syncthreads();
    }
    const float M = sm[0];
    const float inv = 1.f / ss[0];
    for (int i = tid; i < N; i += 256)
        p[i] = __expf(p[i] - M) * inv;
}

// ---------------- column stats: per-feature sum / sumsq (partials) ------------
__global__ void colstats(void)
{
    const int tid = threadIdx.x;
    const int c = blockIdx.x * 128 + (tid & 127);
    const int rl = tid >> 7;                 // 0/1
    const int r0 = blockIdx.y * 256;
    float s = 0.f, q = 0.f;
    for (int r = r0 + rl; r < r0 + 256; r += 2) {
        float v = g_O[(size_t)r * FDIM + c];
        s += v; q += v * v;
    }
    __shared__ float sh[256], shq[256];
    sh[tid] = s; shq[tid] = q;
    __syncthreads();
    if (tid < 128) {
        g_psum[blockIdx.y * FDIM + c] = sh[tid] + sh[tid + 128];
        g_psq [blockIdx.y * FDIM + c] = shq[tid] + shq[tid + 128];
    }
}

__global__ void finalize_stats(void)
{
    const int c = threadIdx.x;
    float s = 0.f, q = 0.f;
    for (int j = 0; j < 32; j++) {
        s += g_psum[j * FDIM + c];
        q += g_psq [j * FDIM + c];
    }
    float mean = s * (1.f / (float)NNODE);
    float var  = q * (1.f / (float)NNODE) - mean * mean;
    g_mean[c] = mean;
    g_rstd[c] = rsqrtf(var + 1e-5f);
}

// ---------------- batchnorm (no affine) + leaky relu -> d_out -----------------
__global__ void normalize_out(float* __restrict__ out)
{
    int idx = blockIdx.x * blockDim.x + threadIdx.x;
    int c = idx & 511;
    float v = (g_O[idx] - g_mean[c]) * g_rstd[c];
    out[idx] = v >= 0.f ? v : 0.01f * v;
}

// ---------------- launch --------------------------------------------------------
extern "C" void kernel_launch(void* const* d_in, const int* in_sizes, int n_in,
                              void* d_out, int out_size)
{
    // Identify inputs by element count (robust to ordering). bias = a_w+a_b is
    // symmetric, so the two scalars need no disambiguation.
    const float* X = nullptr;
    const float* W = nullptr;
    const float* s1 = nullptr;
    const float* s2 = nullptr;
    for (int i = 0; i < n_in; i++) {
        if (in_sizes[i] == NNODE * FDIM)      X = (const float*)d_in[i];
        else if (in_sizes[i] == FDIM * C2)    W = (const float*)d_in[i];
        else if (in_sizes[i] == 1) { if (!s1) s1 = (const float*)d_in[i]; else s2 = (const float*)d_in[i]; }
        // adj (NNODE*NNODE) is unused by the reference module
    }

    float *pC, *pWh, *pT, *pS, *pO;
    cudaGetSymbolAddress((void**)&pC,  g_C);
    cudaGetSymbolAddress((void**)&pWh, g_Wh);
    cudaGetSymbolAddress((void**)&pT,  g_T);
    cudaGetSymbolAddress((void**)&pS,  g_S);
    cudaGetSymbolAddress((void**)&pO,  g_O);

    const dim3 blk(256);

    // 1) C = X @ W                     [8192,512] @ [512,1024]
    sgemm128<false><<<dim3(C2 / 128, NNODE / 128), blk>>>(X, W, pC, nullptr,
                                                          NNODE, C2, FDIM);
    // 2) Wh split; T = tanh(Wh+Ws+bias)
    prep_kernel<<<(NNODE * FDIM) / 256, 256>>>(s1, s2);

    // 3) S = T @ Wh^T                  [8192,512] @ [8192,512]^T
    sgemm128<true><<<dim3(NNODE / 128, NNODE / 128), blk>>>(pT, pWh, pS, nullptr,
                                                            NNODE, NNODE, FDIM);
    // 4) row softmax in place
    softmax_row<<<NNODE, 256>>>(pS, NNODE);

    // 5) O = S @ Wh + X                [8192,8192] @ [8192,512]
    sgemm128<false><<<dim3(FDIM / 128, NNODE / 128), blk>>>(pS, pWh, pO, X,
                                                            NNODE, FDIM, NNODE);
    // 6) batchnorm stats + 7) normalize + leaky relu
    colstats<<<dim3(FDIM / 128, 32), 256>>>();
    finalize_stats<<<1, FDIM>>>();
    normalize_out<<<(NNODE * FDIM) / 256, 256>>>((float*)d_out);
}

// round 15
// speedup vs baseline: 1.2566x; 1.2566x over previous
#include <cuda_runtime.h>
#include <cstdint>
#include <math.h>

#define NNODE 8192
#define FDIM  512
#define C2    1024

// ---------------- scratch (static __device__ — no allocations) ----------------
__device__ float g_C  [(size_t)NNODE * C2];     // X @ W          [8192,1024]
__device__ float g_WT [(size_t)C2 * FDIM];      // W^T            [1024,512]
__device__ float g_Wh [(size_t)NNODE * FDIM];   // Wh             [8192,512]
__device__ float g_T  [(size_t)NNODE * FDIM];   // tanh(Wh+Ws+b)  [8192,512]
__device__ float g_WhT[(size_t)FDIM * NNODE];   // Wh^T           [512,8192]
__device__ float g_S  [(size_t)NNODE * NNODE];  // scores/attn    [8192,8192]
__device__ float g_O  [(size_t)NNODE * FDIM];   // attn@Wh + X
__device__ float g_psum[32 * FDIM];
__device__ float g_psq [32 * FDIM];
__device__ float g_mean[FDIM];
__device__ float g_rstd[FDIM];

// ---------------- helpers ----------------
__device__ __forceinline__ uint32_t smem_u32(const void* p) {
    uint32_t a;
    asm("{ .reg .u64 t; cvta.to.shared.u64 t, %1; cvt.u32.u64 %0, t; }" : "=r"(a) : "l"(p));
    return a;
}

// split fp32 -> (tf32-hi bits, residual bits). HMMA truncates operand low bits,
// so the residual needs no explicit mask.
__device__ __forceinline__ void split2(float v, uint32_t& h, uint32_t& l) {
    uint32_t hv = __float_as_uint(v) & 0xFFFFE000u;
    h = hv;
    l = __float_as_uint(v - __uint_as_float(hv));
}

#define MMA8(d, a, b)                                                        \
    asm volatile("mma.sync.aligned.m16n8k8.row.col.f32.tf32.tf32.f32 "       \
        "{%0,%1,%2,%3}, {%4,%5,%6,%7}, {%8,%9}, {%0,%1,%2,%3};"              \
        : "+f"((d)[0]), "+f"((d)[1]), "+f"((d)[2]), "+f"((d)[3])             \
        : "r"((a)[0]), "r"((a)[1]), "r"((a)[2]), "r"((a)[3]),                \
          "r"((b)[0]), "r"((b)[1]))

#define CP16(dst, src) \
    asm volatile("cp.async.cg.shared.global [%0], [%1], 16;" :: "r"(dst), "l"(src))
#define CP_COMMIT() asm volatile("cp.async.commit_group;" ::: "memory")
#define CP_WAIT1()  asm volatile("cp.async.wait_group 1;"  ::: "memory")

// ---------------- tf32 3-split TN GEMM via mma.sync ----------------------------
// C[M, Ntot-slice] = A[M,K] @ Bt[N,K]^T  (+ optional residual)
// CTA 128x128, BK=32, 8 warps, warp tile 64x32. K % 32 == 0, dims % 128 == 0
// (Ntot=512 uses grid.x=4).
#define BM 128
#define BN 128
#define BK 32
#define KPAD 36                     // floats per smem row (pad 32->36)
#define ATILE (BM * KPAD)           // 4608 floats
#define STAGE_F (2 * ATILE)         // A + B per stage
#define GEMM_SMEM (2 * STAGE_F * 4) // 73728 bytes

__global__ __launch_bounds__(256)
void mma_gemm(const float* __restrict__ A, const float* __restrict__ Bt,
              float* __restrict__ C, const float* __restrict__ resid,
              int Ntot, int K)
{
    extern __shared__ float sm[];
    const int tid  = threadIdx.x;
    const int lane = tid & 31, wid = tid >> 5;
    const int wm = (wid >> 2) * 64;       // warp m-offset in CTA tile
    const int wn = (wid & 3) * 32;        // warp n-offset
    const int gp = lane >> 2;             // groupID (0..7)
    const int tg = lane & 3;              // thread-in-group (0..3)
    const int m0 = blockIdx.y * BM;
    const int n0 = blockIdx.x * BN;

    const uint32_t sbase = smem_u32(sm);
    const int lrow = tid >> 3;            // 0..31 (loader row within 32-row pass)
    const int lc4  = (tid & 7) * 4;       // 0,4,..,28 (k offset, float4)

    float acc[4][4][4];
#pragma unroll
    for (int i = 0; i < 4; i++)
#pragma unroll
        for (int j = 0; j < 4; j++)
#pragma unroll
            for (int q = 0; q < 4; q++) acc[i][j][q] = 0.f;

    const int T = K >> 5;

    // stage loader: 128 rows x 32 floats for A and B (8 float4 per thread)
    auto load_stage = [&](int t, int s) {
        const int k0 = t << 5;
        uint32_t d = sbase + (uint32_t)(s * STAGE_F) * 4;
#pragma unroll
        for (int j = 0; j < 4; j++) {
            int row = lrow + 32 * j;
            CP16(d + (uint32_t)(row * KPAD + lc4) * 4,
                 A + (size_t)(m0 + row) * K + k0 + lc4);
        }
        d += ATILE * 4;
#pragma unroll
        for (int j = 0; j < 4; j++) {
            int row = lrow + 32 * j;
            CP16(d + (uint32_t)(row * KPAD + lc4) * 4,
                 Bt + (size_t)(n0 + row) * K + k0 + lc4);
        }
    };

    load_stage(0, 0);
    CP_COMMIT();

    for (int t = 0; t < T; t++) {
        if (t + 1 < T) load_stage(t + 1, (t + 1) & 1);
        CP_COMMIT();
        CP_WAIT1();
        __syncthreads();

        const float* As = sm + (t & 1) * STAGE_F;
        const float* Bs = As + ATILE;

#pragma unroll
        for (int kf = 0; kf < 4; kf++) {
            const int kb = kf * 8 + tg;
            // B fragments (split once, reused over mf)
            uint32_t bh[4][2], bl[4][2];
#pragma unroll
            for (int nf = 0; nf < 4; nf++) {
                const float* bp = Bs + (wn + nf * 8 + gp) * KPAD + kb;
                split2(bp[0], bh[nf][0], bl[nf][0]);
                split2(bp[4], bh[nf][1], bl[nf][1]);
            }
#pragma unroll
            for (int mf = 0; mf < 4; mf++) {
                const float* ap = As + (wm + mf * 16 + gp) * KPAD + kb;
                uint32_t ah[4], al[4];
                split2(ap[0],            ah[0], al[0]);
                split2(ap[8 * KPAD],     ah[1], al[1]);
                split2(ap[4],            ah[2], al[2]);
                split2(ap[8 * KPAD + 4], ah[3], al[3]);
#pragma unroll
                for (int nf = 0; nf < 4; nf++) {
                    MMA8(acc[mf][nf], ah, bh[nf]);   // hi*hi
                    MMA8(acc[mf][nf], ah, bl[nf]);   // hi*lo
                    MMA8(acc[mf][nf], al, bh[nf]);   // lo*hi
                }
            }
        }
        __syncthreads();
    }

    // epilogue: d0,d1 -> (m, n..n+1), d2,d3 -> (m+8, n..n+1)
#pragma unroll
    for (int mf = 0; mf < 4; mf++) {
#pragma unroll
        for (int nf = 0; nf < 4; nf++) {
            int m = m0 + wm + mf * 16 + gp;
            int n = n0 + wn + nf * 8 + tg * 2;
            size_t i0 = (size_t)m * Ntot + n;
            size_t i1 = (size_t)(m + 8) * Ntot + n;
            float2 v0 = make_float2(acc[mf][nf][0], acc[mf][nf][1]);
            float2 v1 = make_float2(acc[mf][nf][2], acc[mf][nf][3]);
            if (resid) {
                float2 r0 = *(const float2*)(resid + i0);
                float2 r1 = *(const float2*)(resid + i1);
                v0.x += r0.x; v0.y += r0.y;
                v1.x += r1.x; v1.y += r1.y;
            }
            *(float2*)(C + i0) = v0;
            *(float2*)(C + i1) = v1;
        }
    }
}

// ---------------- transpose via 32x32 smem tiles --------------------------------
__global__ void trans_plain(const float* __restrict__ in, float* __restrict__ out,
                            int R, int Cc)
{
    __shared__ float tile[32][33];
    int x = blockIdx.x * 32 + threadIdx.x;
    int y = blockIdx.y * 32 + threadIdx.y;
    tile[threadIdx.y][threadIdx.x] = in[(size_t)y * Cc + x];
    __syncthreads();
    int ox = blockIdx.y * 32 + threadIdx.x;
    int oy = blockIdx.x * 32 + threadIdx.y;
    out[(size_t)oy * R + ox] = tile[threadIdx.x][threadIdx.y];
}

// ---------------- split C -> Wh, T = tanh(Wh + Ws + bias) -----------------------
__global__ void prep_kernel(const float* __restrict__ aw, const float* __restrict__ ab)
{
    const float bias = aw[0] + ab[0];
    int idx = blockIdx.x * blockDim.x + threadIdx.x;
    int row = idx >> 9, col = idx & 511;
    float wh = g_C[(size_t)row * C2 + col];
    float ws = g_C[(size_t)row * C2 + col + FDIM];
    g_Wh[idx] = wh;
    g_T[idx]  = tanhf(wh + ws + bias);
}

// ---------------- in-place row softmax ------------------------------------------
__global__ void softmax_row(float* __restrict__ S, int N)
{
    const int row = blockIdx.x;
    float* p = S + (size_t)row * N;
    const int tid = threadIdx.x;

    float m = -1e30f, s = 0.f;
    for (int i = tid; i < N; i += 256) {
        float x = p[i];
        float mn = fmaxf(m, x);
        s = s * __expf(m - mn) + __expf(x - mn);
        m = mn;
    }
    __shared__ float smx[256], ssm[256];
    smx[tid] = m; ssm[tid] = s;
    __syncthreads();
    for (int off = 128; off > 0; off >>= 1) {
        if (tid < off) {
            float m2 = smx[tid + off], s2 = ssm[tid + off];
            float mn = fmaxf(smx[tid], m2);
            ssm[tid] = ssm[tid] * __expf(smx[tid] - mn) + s2 * __expf(m2 - mn);
            smx[tid] = mn;
        }
        __syncthreads();
    }
    const float M = smx[0];
    const float inv = 1.f / ssm[0];
    for (int i = tid; i < N; i += 256)
        p[i] = __expf(p[i] - M) * inv;
}

// ---------------- batchnorm stats + normalize ------------------------------------
__global__ void colstats(void)
{
    const int tid = threadIdx.x;
    const int c = blockIdx.x * 128 + (tid & 127);
    const int rl = tid >> 7;
    const int r0 = blockIdx.y * 256;
    float s = 0.f, q = 0.f;
    for (int r = r0 + rl; r < r0 + 256; r += 2) {
        float v = g_O[(size_t)r * FDIM + c];
        s += v; q += v * v;
    }
    __shared__ float sh[256], shq[256];
    sh[tid] = s; shq[tid] = q;
    __syncthreads();
    if (tid < 128) {
        g_psum[blockIdx.y * FDIM + c] = sh[tid] + sh[tid + 128];
        g_psq [blockIdx.y * FDIM + c] = shq[tid] + shq[tid + 128];
    }
}

__global__ void finalize_stats(void)
{
    const int c = threadIdx.x;
    float s = 0.f, q = 0.f;
    for (int j = 0; j < 32; j++) {
        s += g_psum[j * FDIM + c];
        q += g_psq [j * FDIM + c];
    }
    float mean = s * (1.f / (float)NNODE);
    float var  = q * (1.f / (float)NNODE) - mean * mean;
    g_mean[c] = mean;
    g_rstd[c] = rsqrtf(var + 1e-5f);
}

__global__ void normalize_out(float* __restrict__ out)
{
    int idx = blockIdx.x * blockDim.x + threadIdx.x;
    int c = idx & 511;
    float v = (g_O[idx] - g_mean[c]) * g_rstd[c];
    out[idx] = v >= 0.f ? v : 0.01f * v;
}

// ---------------- launch ----------------------------------------------------------
extern "C" void kernel_launch(void* const* d_in, const int* in_sizes, int n_in,
                              void* d_out, int out_size)
{
    const float *X = nullptr, *W = nullptr, *s1 = nullptr, *s2 = nullptr;
    for (int i = 0; i < n_in; i++) {
        if (in_sizes[i] == NNODE * FDIM)   X = (const float*)d_in[i];
        else if (in_sizes[i] == FDIM * C2) W = (const float*)d_in[i];
        else if (in_sizes[i] == 1) { if (!s1) s1 = (const float*)d_in[i]; else s2 = (const float*)d_in[i]; }
    }

    float *pC, *pWT, *pWh, *pT, *pWhT, *pS, *pO;
    cudaGetSymbolAddress((void**)&pC,   g_C);
    cudaGetSymbolAddress((void**)&pWT,  g_WT);
    cudaGetSymbolAddress((void**)&pWh,  g_Wh);
    cudaGetSymbolAddress((void**)&pT,   g_T);
    cudaGetSymbolAddress((void**)&pWhT, g_WhT);
    cudaGetSymbolAddress((void**)&pS,   g_S);
    cudaGetSymbolAddress((void**)&pO,   g_O);

    cudaFuncSetAttribute(mma_gemm, cudaFuncAttributeMaxDynamicSharedMemorySize, GEMM_SMEM);

    // 0) W^T  [512,1024] -> [1024,512]
    trans_plain<<<dim3(C2 / 32, FDIM / 32), dim3(32, 32)>>>(W, pWT, FDIM, C2);

    // 1) C = X @ W            M=8192 Ntot=1024 K=512
    mma_gemm<<<dim3(C2 / BN, NNODE / BM), 256, GEMM_SMEM>>>(X, pWT, pC, nullptr,
                                                            C2, FDIM);
    // 2) Wh split; T = tanh(Wh+Ws+bias)
    prep_kernel<<<(NNODE * FDIM) / 256, 256>>>(s1, s2);

    // 2b) Wh^T for GEMM5
    trans_plain<<<dim3(FDIM / 32, NNODE / 32), dim3(32, 32)>>>(pWh, pWhT, NNODE, FDIM);

    // 3) S = T @ Wh^T         M=8192 Ntot=8192 K=512
    mma_gemm<<<dim3(NNODE / BN, NNODE / BM), 256, GEMM_SMEM>>>(pT, pWh, pS, nullptr,
                                                               NNODE, FDIM);
    // 4) row softmax in place
    softmax_row<<<NNODE, 256>>>(pS, NNODE);

    // 5) O = attn @ Wh + X    M=8192 Ntot=512 K=8192
    mma_gemm<<<dim3(FDIM / BN, NNODE / BM), 256, GEMM_SMEM>>>(pS, pWhT, pO, X,
                                                              FDIM, NNODE);
    // 6) batchnorm + leaky relu
    colstats<<<dim3(FDIM / 128, 32), 256>>>();
    finalize_stats<<<1, FDIM>>>();
    normalize_out<<<(NNODE * FDIM) / 256, 256>>>((float*)d_out);
}

// round 16
// speedup vs baseline: 1.6577x; 1.3193x over previous
#include <cuda_runtime.h>
#include <cuda_fp16.h>
#include <cstdint>
#include <math.h>

#define NNODE 8192
#define FDIM  512
#define C2    1024

// ---------------- scratch (static __device__ — no allocations) ----------------
__device__ float  g_C  [(size_t)NNODE * C2];      // X @ W           [8192,1024]
__device__ float  g_S  [(size_t)NNODE * NNODE];   // scores fp32     [8192,8192]
__device__ float  g_O  [(size_t)NNODE * FDIM];    // attn@Wh + X
__device__ __half g_Xh [(size_t)NNODE * FDIM];    // X split hi/lo
__device__ __half g_Xl [(size_t)NNODE * FDIM];
__device__ __half g_WTh[(size_t)C2 * FDIM];       // W^T split       [1024,512]
__device__ __half g_WTl[(size_t)C2 * FDIM];
__device__ __half g_Whh[(size_t)NNODE * FDIM];    // Wh split        [8192,512]
__device__ __half g_Whl[(size_t)NNODE * FDIM];
__device__ __half g_Th [(size_t)NNODE * FDIM];    // tanh(.) split   [8192,512]
__device__ __half g_Tl [(size_t)NNODE * FDIM];
__device__ __half g_WhTh[(size_t)FDIM * NNODE];   // Wh^T split      [512,8192]
__device__ __half g_WhTl[(size_t)FDIM * NNODE];
__device__ __half g_Sh [(size_t)NNODE * NNODE];   // attn split      [8192,8192]
__device__ __half g_Sl [(size_t)NNODE * NNODE];
__device__ float g_psum[32 * FDIM];
__device__ float g_psq [32 * FDIM];
__device__ float g_mean[FDIM];
__device__ float g_rstd[FDIM];

// ---------------- helpers ----------------
__device__ __forceinline__ uint32_t smem_u32(const void* p) {
    uint32_t a;
    asm("{ .reg .u64 t; cvta.to.shared.u64 t, %1; cvt.u32.u64 %0, t; }" : "=r"(a) : "l"(p));
    return a;
}

#define MMAH(d, a, b)                                                        \
    asm volatile("mma.sync.aligned.m16n8k16.row.col.f32.f16.f16.f32 "        \
        "{%0,%1,%2,%3}, {%4,%5,%6,%7}, {%8,%9}, {%0,%1,%2,%3};"              \
        : "+f"((d)[0]), "+f"((d)[1]), "+f"((d)[2]), "+f"((d)[3])             \
        : "r"((a)[0]), "r"((a)[1]), "r"((a)[2]), "r"((a)[3]),                \
          "r"((b)[0]), "r"((b)[1]))

#define CP16(dst, src) \
    asm volatile("cp.async.cg.shared.global [%0], [%1], 16;" :: "r"(dst), "l"(src))
#define CP_COMMIT() asm volatile("cp.async.commit_group;" ::: "memory")
#define CP_WAIT1()  asm volatile("cp.async.wait_group 1;"  ::: "memory")

// ---------------- fp16x3 TN GEMM via mma.sync.m16n8k16 -------------------------
// C[M, Ntot-slice] = A[M,K] @ Bt[N,K]^T (+ residual), operands pre-split hi/lo f16.
// CTA 128x128, BK=32, 8 warps, warp tile 64x32.
#define BM 128
#define BN 128
#define BK 32
#define RB 80                  // bytes per smem row: 32 halves (64B) + 16B pad
#define TILE_B (BM * RB)       // 10240
#define OFF_AH 0
#define OFF_AL 10240
#define OFF_BH 20480
#define OFF_BL 30720
#define STAGE_B 40960
#define GEMM_SMEM (2 * STAGE_B)  // 81920

__global__ __launch_bounds__(256)
void mma_gemm(const __half* __restrict__ Ah, const __half* __restrict__ Al,
              const __half* __restrict__ Bh, const __half* __restrict__ Bl,
              float* __restrict__ C, const float* __restrict__ resid,
              int Ntot, int K)
{
    extern __shared__ char smem[];
    const int tid  = threadIdx.x;
    const int lane = tid & 31, wid = tid >> 5;
    const int wm = (wid >> 2) * 64;
    const int wn = (wid & 3) * 32;
    const int gp = lane >> 2;             // groupID 0..7
    const int tg = lane & 3;              // thread-in-group 0..3
    const int m0 = blockIdx.y * BM;
    const int n0 = blockIdx.x * BN;

    const uint32_t sbase = smem_u32(smem);
    const int lrow = tid >> 1;            // 0..127
    const int lcol = (tid & 1) * 16;      // halves: 0 or 16

    float acc[4][4][4];
#pragma unroll
    for (int i = 0; i < 4; i++)
#pragma unroll
        for (int j = 0; j < 4; j++)
#pragma unroll
            for (int q = 0; q < 4; q++) acc[i][j][q] = 0.f;

    const int T = K >> 5;

    // stage loader: 4 tiles x 128 rows x 32 halves; 8 cp.async per thread
    auto load_stage = [&](int t, int s) {
        const int k0 = t << 5;
        const uint32_t d = sbase + (uint32_t)(s * STAGE_B) + (uint32_t)(lrow * RB + lcol * 2);
        const size_t ga = (size_t)(m0 + lrow) * K + k0 + lcol;
        const size_t gb = (size_t)(n0 + lrow) * K + k0 + lcol;
        CP16(d + OFF_AH,      Ah + ga);
        CP16(d + OFF_AH + 16, Ah + ga + 8);
        CP16(d + OFF_AL,      Al + ga);
        CP16(d + OFF_AL + 16, Al + ga + 8);
        CP16(d + OFF_BH,      Bh + gb);
        CP16(d + OFF_BH + 16, Bh + gb + 8);
        CP16(d + OFF_BL,      Bl + gb);
        CP16(d + OFF_BL + 16, Bl + gb + 8);
    };

    load_stage(0, 0);
    CP_COMMIT();

    for (int t = 0; t < T; t++) {
        if (t + 1 < T) load_stage(t + 1, (t + 1) & 1);
        CP_COMMIT();
        CP_WAIT1();
        __syncthreads();

        const char* base = smem + (t & 1) * STAGE_B;

#pragma unroll
        for (int ks = 0; ks < 2; ks++) {
            const int kb = ks * 32;       // byte offset of k16 step (16 halves)

            // B fragments for all nf (hi + lo), reused across mf
            uint32_t bh[4][2], bl[4][2];
#pragma unroll
            for (int nf = 0; nf < 4; nf++) {
                const char* bp = base + OFF_BH + (wn + nf * 8 + gp) * RB + tg * 4 + kb;
                bh[nf][0] = *(const uint32_t*)bp;
                bh[nf][1] = *(const uint32_t*)(bp + 16);
                const char* bq = bp + (OFF_BL - OFF_BH);
                bl[nf][0] = *(const uint32_t*)bq;
                bl[nf][1] = *(const uint32_t*)(bq + 16);
            }
#pragma unroll
            for (int mf = 0; mf < 4; mf++) {
                const char* ap = base + OFF_AH + (wm + mf * 16 + gp) * RB + tg * 4 + kb;
                uint32_t ah[4], al[4];
                ah[0] = *(const uint32_t*)ap;
                ah[1] = *(const uint32_t*)(ap + 8 * RB);
                ah[2] = *(const uint32_t*)(ap + 16);
                ah[3] = *(const uint32_t*)(ap + 8 * RB + 16);
                const char* aq = ap + (OFF_AL - OFF_AH);
                al[0] = *(const uint32_t*)aq;
                al[1] = *(const uint32_t*)(aq + 8 * RB);
                al[2] = *(const uint32_t*)(aq + 16);
                al[3] = *(const uint32_t*)(aq + 8 * RB + 16);
#pragma unroll
                for (int nf = 0; nf < 4; nf++) {
                    MMAH(acc[mf][nf], ah, bh[nf]);   // hi*hi
                    MMAH(acc[mf][nf], ah, bl[nf]);   // hi*lo
                    MMAH(acc[mf][nf], al, bh[nf]);   // lo*hi
                }
            }
        }
        __syncthreads();
    }

    // epilogue: d0,d1 -> (m, n..n+1); d2,d3 -> (m+8, n..n+1)
#pragma unroll
    for (int mf = 0; mf < 4; mf++) {
#pragma unroll
        for (int nf = 0; nf < 4; nf++) {
            int m = m0 + wm + mf * 16 + gp;
            int n = n0 + wn + nf * 8 + tg * 2;
            size_t i0 = (size_t)m * Ntot + n;
            size_t i1 = (size_t)(m + 8) * Ntot + n;
            float2 v0 = make_float2(acc[mf][nf][0], acc[mf][nf][1]);
            float2 v1 = make_float2(acc[mf][nf][2], acc[mf][nf][3]);
            if (resid) {
                float2 r0 = *(const float2*)(resid + i0);
                float2 r1 = *(const float2*)(resid + i1);
                v0.x += r0.x; v0.y += r0.y;
                v1.x += r1.x; v1.y += r1.y;
            }
            *(float2*)(C + i0) = v0;
            *(float2*)(C + i1) = v1;
        }
    }
}

// ---------------- split f32 -> f16 hi/lo ----------------------------------------
__device__ __forceinline__ void hsplit(float x, __half& h, __half& l) {
    h = __float2half_rn(x);
    l = __float2half_rn(x - __half2float(h));
}

__global__ void split_h(const float* __restrict__ in, __half* __restrict__ oh,
                        __half* __restrict__ ol)
{
    int i = blockIdx.x * blockDim.x + threadIdx.x;
    __half h, l;
    hsplit(in[i], h, l);
    oh[i] = h; ol[i] = l;
}

// ---------------- transpose f32 -> split halves ----------------------------------
__global__ void trans_split_h(const float* __restrict__ in, __half* __restrict__ oh,
                              __half* __restrict__ ol, int R, int Cc)
{
    __shared__ float tile[32][33];
    int x = blockIdx.x * 32 + threadIdx.x;
    int y = blockIdx.y * 32 + threadIdx.y;
    tile[threadIdx.y][threadIdx.x] = in[(size_t)y * Cc + x];
    __syncthreads();
    int ox = blockIdx.y * 32 + threadIdx.x;
    int oy = blockIdx.x * 32 + threadIdx.y;
    __half h, l;
    hsplit(tile[threadIdx.x][threadIdx.y], h, l);
    oh[(size_t)oy * R + ox] = h;
    ol[(size_t)oy * R + ox] = l;
}

// ---------------- transpose halves ------------------------------------------------
__global__ void trans_h(const __half* __restrict__ in, __half* __restrict__ out,
                        int R, int Cc)
{
    __shared__ __half tile[32][34];
    int x = blockIdx.x * 32 + threadIdx.x;
    int y = blockIdx.y * 32 + threadIdx.y;
    tile[threadIdx.y][threadIdx.x] = in[(size_t)y * Cc + x];
    __syncthreads();
    int ox = blockIdx.y * 32 + threadIdx.x;
    int oy = blockIdx.x * 32 + threadIdx.y;
    out[(size_t)oy * R + ox] = tile[threadIdx.x][threadIdx.y];
}

// ---------------- C -> Wh splits, T = tanh(Wh+Ws+bias) splits --------------------
__global__ void prep_kernel(const float* __restrict__ aw, const float* __restrict__ ab)
{
    const float bias = aw[0] + ab[0];
    int idx = blockIdx.x * blockDim.x + threadIdx.x;
    int row = idx >> 9, col = idx & 511;
    float wh = g_C[(size_t)row * C2 + col];
    float ws = g_C[(size_t)row * C2 + col + FDIM];
    float t = tanhf(wh + ws + bias);
    __half h, l;
    hsplit(wh, h, l); g_Whh[idx] = h; g_Whl[idx] = l;
    hsplit(t,  h, l); g_Th[idx]  = h; g_Tl[idx]  = l;
}

// ---------------- row softmax -> attn hi/lo halves --------------------------------
__global__ void softmax_row(const float* __restrict__ S, __half* __restrict__ Sh,
                            __half* __restrict__ Sl, int N)
{
    const int row = blockIdx.x;
    const float* p = S + (size_t)row * N;
    const int tid = threadIdx.x;

    float m = -1e30f, s = 0.f;
    for (int i = tid; i < N; i += 256) {
        float x = p[i];
        float mn = fmaxf(m, x);
        s = s * __expf(m - mn) + __expf(x - mn);
        m = mn;
    }
    __shared__ float smx[256], ssm[256];
    smx[tid] = m; ssm[tid] = s;
    __syncthreads();
    for (int off = 128; off > 0; off >>= 1) {
        if (tid < off) {
            float m2 = smx[tid + off], s2 = ssm[tid + off];
            float mn = fmaxf(smx[tid], m2);
            ssm[tid] = ssm[tid] * __expf(smx[tid] - mn) + s2 * __expf(m2 - mn);
            smx[tid] = mn;
        }
        __syncthreads();
    }
    const float M = smx[0];
    const float inv = 1.f / ssm[0];
    size_t base = (size_t)row * N;
    for (int i = tid; i < N; i += 256) {
        float e = __expf(p[i] - M) * inv;
        __half h, l;
        hsplit(e, h, l);
        Sh[base + i] = h;
        Sl[base + i] = l;
    }
}

// ---------------- batchnorm stats + normalize ------------------------------------
__global__ void colstats(void)
{
    const int tid = threadIdx.x;
    const int c = blockIdx.x * 128 + (tid & 127);
    const int rl = tid >> 7;
    const int r0 = blockIdx.y * 256;
    float s = 0.f, q = 0.f;
    for (int r = r0 + rl; r < r0 + 256; r += 2) {
        float v = g_O[(size_t)r * FDIM + c];
        s += v; q += v * v;
    }
    __shared__ float sh[256], shq[256];
    sh[tid] = s; shq[tid] = q;
    __syncthreads();
    if (tid < 128) {
        g_psum[blockIdx.y * FDIM + c] = sh[tid] + sh[tid + 128];
        g_psq [blockIdx.y * FDIM + c] = shq[tid] + shq[tid + 128];
    }
}

__global__ void finalize_stats(void)
{
    const int c = threadIdx.x;
    float s = 0.f, q = 0.f;
    for (int j = 0; j < 32; j++) {
        s += g_psum[j * FDIM + c];
        q += g_psq [j * FDIM + c];
    }
    float mean = s * (1.f / (float)NNODE);
    float var  = q * (1.f / (float)NNODE) - mean * mean;
    g_mean[c] = mean;
    g_rstd[c] = rsqrtf(var + 1e-5f);
}

__global__ void normalize_out(float* __restrict__ out)
{
    int idx = blockIdx.x * blockDim.x + threadIdx.x;
    int c = idx & 511;
    float v = (g_O[idx] - g_mean[c]) * g_rstd[c];
    out[idx] = v >= 0.f ? v : 0.01f * v;
}

// ---------------- launch ----------------------------------------------------------
extern "C" void kernel_launch(void* const* d_in, const int* in_sizes, int n_in,
                              void* d_out, int out_size)
{
    const float *X = nullptr, *W = nullptr, *s1 = nullptr, *s2 = nullptr;
    for (int i = 0; i < n_in; i++) {
        if (in_sizes[i] == NNODE * FDIM)   X = (const float*)d_in[i];
        else if (in_sizes[i] == FDIM * C2) W = (const float*)d_in[i];
        else if (in_sizes[i] == 1) { if (!s1) s1 = (const float*)d_in[i]; else s2 = (const float*)d_in[i]; }
    }

    float *pC, *pS, *pO;
    __half *pXh, *pXl, *pWTh, *pWTl, *pWhh, *pWhl, *pTh, *pTl, *pWhTh, *pWhTl, *pSh, *pSl;
    cudaGetSymbolAddress((void**)&pC, g_C);
    cudaGetSymbolAddress((void**)&pS, g_S);
    cudaGetSymbolAddress((void**)&pO, g_O);
    cudaGetSymbolAddress((void**)&pXh, g_Xh);     cudaGetSymbolAddress((void**)&pXl, g_Xl);
    cudaGetSymbolAddress((void**)&pWTh, g_WTh);   cudaGetSymbolAddress((void**)&pWTl, g_WTl);
    cudaGetSymbolAddress((void**)&pWhh, g_Whh);   cudaGetSymbolAddress((void**)&pWhl, g_Whl);
    cudaGetSymbolAddress((void**)&pTh, g_Th);     cudaGetSymbolAddress((void**)&pTl, g_Tl);
    cudaGetSymbolAddress((void**)&pWhTh, g_WhTh); cudaGetSymbolAddress((void**)&pWhTl, g_WhTl);
    cudaGetSymbolAddress((void**)&pSh, g_Sh);     cudaGetSymbolAddress((void**)&pSl, g_Sl);

    cudaFuncSetAttribute(mma_gemm, cudaFuncAttributeMaxDynamicSharedMemorySize, GEMM_SMEM);

    // 0) operand prep
    split_h<<<(NNODE * FDIM) / 256, 256>>>(X, pXh, pXl);
    trans_split_h<<<dim3(C2 / 32, FDIM / 32), dim3(32, 32)>>>(W, pWTh, pWTl, FDIM, C2);

    // 1) C = X @ W            M=8192 Ntot=1024 K=512
    mma_gemm<<<dim3(C2 / BN, NNODE / BM), 256, GEMM_SMEM>>>(pXh, pXl, pWTh, pWTl,
                                                            pC, nullptr, C2, FDIM);
    // 2) Wh/T splits
    prep_kernel<<<(NNODE * FDIM) / 256, 256>>>(s1, s2);

    // 2b) Wh^T splits for GEMM5
    trans_h<<<dim3(FDIM / 32, NNODE / 32), dim3(32, 32)>>>(pWhh, pWhTh, NNODE, FDIM);
    trans_h<<<dim3(FDIM / 32, NNODE / 32), dim3(32, 32)>>>(pWhl, pWhTl, NNODE, FDIM);

    // 3) S = T @ Wh^T         M=8192 Ntot=8192 K=512
    mma_gemm<<<dim3(NNODE / BN, NNODE / BM), 256, GEMM_SMEM>>>(pTh, pTl, pWhh, pWhl,
                                                               pS, nullptr, NNODE, FDIM);
    // 4) softmax -> attn hi/lo
    softmax_row<<<NNODE, 256>>>(pS, pSh, pSl, NNODE);

    // 5) O = attn @ Wh + X    M=8192 Ntot=512 K=8192
    mma_gemm<<<dim3(FDIM / BN, NNODE / BM), 256, GEMM_SMEM>>>(pSh, pSl, pWhTh, pWhTl,
                                                              pO, X, FDIM, NNODE);
    // 6) batchnorm + leaky relu
    colstats<<<dim3(FDIM / 128, 32), 256>>>();
    finalize_stats<<<1, FDIM>>>();
    normalize_out<<<(NNODE * FDIM) / 256, 256>>>((float*)d_out);
}